// round 1
// baseline (speedup 1.0000x reference)
#include <cuda_runtime.h>
#include <cub/block/block_radix_sort.cuh>

#define B_SZ   8
#define NFULL  4096
#define NLAT   1024
#define CDIM   256
#define HEADS  8
#define VDIM   32

// ---------------- scratch (static device arrays; no allocation) ----------------
__device__ float g_bufA[B_SZ * NFULL * CDIM];   // 33.5 MB full-res
__device__ float g_bufB[B_SZ * NFULL * CDIM];   // 33.5 MB full-res
__device__ float g_bufL0[B_SZ * NLAT * CDIM];   // 8.4 MB latent
__device__ float g_bufL1[B_SZ * NLAT * CDIM];
__device__ float g_bufL2[B_SZ * NLAT * CDIM];
__device__ float g_att[HEADS * NFULL * NLAT];   // 134 MB (max att size)
__device__ float g_vt [HEADS * NFULL * CDIM];   // 33.5 MB value-transposed [H, Nk, B*VD]
__device__ float g_w2 [CDIM * CDIM];            // repacked per-head value weights

// 0.25*pi*(1-1e-7), rounded to fp32 exactly like jax's weak-typed scalar
__device__ __constant__ float KQ = (float)(0.25 * 3.14159265358979323846 * (1.0 - 1e-7));

__device__ __forceinline__ float gelu_f(float x) {
    float x3 = x * x * x;
    return 0.5f * x * (1.0f + tanhf(0.7978845608028654f * (x + 0.044715f * x3)));
}

// ---------------- encoder: h = gelu(x[...,4] @ W[4,256] + b) ----------------
__global__ void encoder_k(const float* __restrict__ x, const float* __restrict__ w,
                          const float* __restrict__ b, float* __restrict__ out) {
    long row = blockIdx.x;                 // b*NFULL + n
    int c = threadIdx.x;                   // 0..255
    const float* xr = x + row * 4;
    float acc = b[c] + xr[0] * w[c] + xr[1] * w[256 + c]
                     + xr[2] * w[512 + c] + xr[3] * w[768 + c];
    out[row * CDIM + c] = gelu_f(acc);
}

// ---------------- repack value weights: w[h,j,k] -> w2[j, h*32+k] ----------------
__global__ void repack_w_k(const float* __restrict__ w, float* __restrict__ w2) {
    int i = blockIdx.x * 256 + threadIdx.x;   // 65536
    int c = i & 255, j = i >> 8;
    int h = c >> 5, k = c & 31;
    w2[i] = w[h * (CDIM * VDIM) + j * VDIM + k];
}

// ---------------- unmasked attention softmax: att = softmax(-md*scale) ----------------
template <int L>
__global__ void __launch_bounds__(256) softmax_k(const float* __restrict__ md,
                                                 const float* __restrict__ r,
                                                 float* __restrict__ att, int Nq) {
    const int E = L / 256;
    __shared__ float red[256];
    long row = blockIdx.x;                  // h*Nq + q
    int h = (int)(row / Nq);
    float scale = tanf(KQ * (1.0f + sinf(r[h])));
    const float* src = md + row * (long)L;
    int tid = threadIdx.x;
    float v[E];
    float mn = 3.4e38f;
    #pragma unroll
    for (int e = 0; e < E; e++) { v[e] = src[tid + 256 * e] * scale; mn = fminf(mn, v[e]); }
    red[tid] = mn; __syncthreads();
    for (int o = 128; o > 0; o >>= 1) { if (tid < o) red[tid] = fminf(red[tid], red[tid + o]); __syncthreads(); }
    mn = red[0]; __syncthreads();
    float s = 0.0f;
    #pragma unroll
    for (int e = 0; e < E; e++) { v[e] = expf(mn - v[e]); s += v[e]; }
    red[tid] = s; __syncthreads();
    for (int o = 128; o > 0; o >>= 1) { if (tid < o) red[tid] += red[tid + o]; __syncthreads(); }
    float inv = 1.0f / red[0];
    #pragma unroll
    for (int e = 0; e < E; e++) att[row * (long)L + tid + 256 * e] = v[e] * inv;
}

// ---------------- percentile-masked softmax (P_LOC=30, L=1024) ----------------
// keep-set == {307 smallest}  (thr in [s306, s307) => sd<=thr  <=>  sd<=s306)
__global__ void __launch_bounds__(256) pct_att_k(const float* __restrict__ md,
                                                 const float* __restrict__ r,
                                                 float* __restrict__ att) {
    const int L = 1024;
    typedef cub::BlockRadixSort<float, 256, 4> Sort;
    __shared__ typename Sort::TempStorage sort_tmp;
    __shared__ float orig[L];
    __shared__ float red[256];
    __shared__ float sh_thr, sh_min;
    int row = blockIdx.x;                   // h*1024 + q
    int h = row >> 10;
    float scale = tanf(KQ * (1.0f + sinf(r[h])));
    int tid = threadIdx.x;
    const float* src = md + (long)row * L;
    float items[4];
    #pragma unroll
    for (int i = 0; i < 4; i++) {
        float v = src[tid * 4 + i] * scale;
        items[i] = v; orig[tid * 4 + i] = v;
    }
    __syncthreads();
    Sort(sort_tmp).Sort(items);             // blocked: thread t holds sorted[4t..4t+3]
    if (tid == 76) sh_thr = items[2];       // sorted[306]
    if (tid == 0)  sh_min = items[0];       // sorted[0]
    __syncthreads();
    float thr = sh_thr, mn = sh_min;
    float vals[4]; float s = 0.0f;
    #pragma unroll
    for (int i = 0; i < 4; i++) {
        float v = orig[tid * 4 + i];
        float e = (v <= thr) ? expf(mn - v) : 0.0f;
        vals[i] = e; s += e;
    }
    red[tid] = s; __syncthreads();
    for (int o = 128; o > 0; o >>= 1) { if (tid < o) red[tid] += red[tid + o]; __syncthreads(); }
    float inv = 1.0f / red[0];
    #pragma unroll
    for (int i = 0; i < 4; i++) att[(long)row * L + tid * 4 + i] = vals[i] * inv;
}

// ---------------- generic tiled fp32 GEMM, 64x64x16, 256 thr, 4x4 per thread ----------------
// MODE 0: C[r*N+c] = gelu(acc + bias[c])
// MODE 1: C[r*N+c] = acc + bias[c]
// MODE 2: C[r*N+c] = gelu(acc + bias[c] + other[r*N+c])
// MODE 3: value-transpose store: h=c>>5,k=c&31,b=r/Nn,n=r%Nn -> C[((h*Nn+n)*B_SZ+b)*32+k]
// MODE 4: att@value: b=c>>5,k=c&31 -> C[((long)b*M + r)*256 + z*32 + k] = gelu(acc)
template <int MODE>
__global__ void __launch_bounds__(256) gemm_k(const float* __restrict__ A,
                                              const float* __restrict__ Bm,
                                              float* __restrict__ C,
                                              const float* __restrict__ bias,
                                              const float* __restrict__ other,
                                              int M, int N, int K,
                                              long sAz, long sBz, int Nn) {
    A  += (long)blockIdx.z * sAz;
    Bm += (long)blockIdx.z * sBz;
    __shared__ float As[16][68];
    __shared__ float Bs[16][64];
    int tid = threadIdx.x;
    int tx = tid & 15, ty = tid >> 4;
    int m0 = blockIdx.y * 64, n0 = blockIdx.x * 64;
    int am = tid >> 2, ak = (tid & 3) * 4;      // A: 64 m-rows x 16 k
    int bk = tid >> 4, bn = (tid & 15) * 4;     // B: 16 k-rows x 64 n
    float acc[4][4] = {};
    for (int k0 = 0; k0 < K; k0 += 16) {
        float4 av = *(const float4*)&A[(long)(m0 + am) * K + k0 + ak];
        float4 bv = *(const float4*)&Bm[(long)(k0 + bk) * N + n0 + bn];
        As[ak + 0][am] = av.x; As[ak + 1][am] = av.y;
        As[ak + 2][am] = av.z; As[ak + 3][am] = av.w;
        *(float4*)&Bs[bk][bn] = bv;
        __syncthreads();
        #pragma unroll
        for (int k = 0; k < 16; k++) {
            float4 a = *(const float4*)&As[k][ty * 4];
            float4 b = *(const float4*)&Bs[k][tx * 4];
            acc[0][0] += a.x * b.x; acc[0][1] += a.x * b.y; acc[0][2] += a.x * b.z; acc[0][3] += a.x * b.w;
            acc[1][0] += a.y * b.x; acc[1][1] += a.y * b.y; acc[1][2] += a.y * b.z; acc[1][3] += a.y * b.w;
            acc[2][0] += a.z * b.x; acc[2][1] += a.z * b.y; acc[2][2] += a.z * b.z; acc[2][3] += a.z * b.w;
            acc[3][0] += a.w * b.x; acc[3][1] += a.w * b.y; acc[3][2] += a.w * b.z; acc[3][3] += a.w * b.w;
        }
        __syncthreads();
    }
    #pragma unroll
    for (int i = 0; i < 4; i++) {
        int r = m0 + ty * 4 + i;
        #pragma unroll
        for (int j = 0; j < 4; j++) {
            int c = n0 + tx * 4 + j;
            float v = acc[i][j];
            if (MODE == 0) {
                C[(long)r * N + c] = gelu_f(v + bias[c]);
            } else if (MODE == 1) {
                C[(long)r * N + c] = v + bias[c];
            } else if (MODE == 2) {
                C[(long)r * N + c] = gelu_f(v + bias[c] + other[(long)r * N + c]);
            } else if (MODE == 3) {
                int hh = c >> 5, kk = c & 31;
                int bb = r / Nn, nn = r % Nn;
                C[(((long)hh * Nn + nn) * B_SZ + bb) * VDIM + kk] = v;
            } else { // MODE 4
                int bb = c >> 5, kk = c & 31;
                C[((long)bb * M + r) * CDIM + blockIdx.z * VDIM + kk] = gelu_f(v);
            }
        }
    }
}

// ---------------- final projection: out[row] = h[row,:]@w[:,1] + b ----------------
__global__ void final_k(const float* __restrict__ h, const float* __restrict__ w,
                        const float* __restrict__ b, float* __restrict__ out) {
    int row = blockIdx.x * 8 + (threadIdx.x >> 5);
    int lane = threadIdx.x & 31;
    const float* hr = h + (long)row * CDIM;
    float acc = 0.0f;
    #pragma unroll
    for (int c = lane; c < CDIM; c += 32) acc += hr[c] * w[c];
    #pragma unroll
    for (int o = 16; o > 0; o >>= 1) acc += __shfl_down_sync(0xffffffffu, acc, o);
    if (lane == 0) out[row] = acc + b[0];
}

// ---------------- host orchestration ----------------
static float* sym(const void* s) {
    void* p = nullptr;
    cudaGetSymbolAddress(&p, s);
    return (float*)p;
}

extern "C" void kernel_launch(void* const* d_in, const int* in_sizes, int n_in,
                              void* d_out, int out_size) {
    const float* x         = (const float*)d_in[0];
    const float* m_down    = (const float*)d_in[1];
    const float* m_p0      = (const float*)d_in[2];
    const float* m_p1      = (const float*)d_in[3];
    const float* m_up      = (const float*)d_in[4];
    const float* en_w      = (const float*)d_in[5];
    const float* en_b      = (const float*)d_in[6];
    const float* down_r    = (const float*)d_in[7];
    const float* down_w    = (const float*)d_in[8];
    const float* pa_r[2]   = {(const float*)d_in[9],  (const float*)d_in[17]};
    const float* pa_w[2]   = {(const float*)d_in[10], (const float*)d_in[18]};
    const float* f1w[2]    = {(const float*)d_in[11], (const float*)d_in[19]};
    const float* f1b[2]    = {(const float*)d_in[12], (const float*)d_in[20]};
    const float* f2w[2]    = {(const float*)d_in[13], (const float*)d_in[21]};
    const float* f2b[2]    = {(const float*)d_in[14], (const float*)d_in[22]};
    const float* rw[2]     = {(const float*)d_in[15], (const float*)d_in[23]};
    const float* rb[2]     = {(const float*)d_in[16], (const float*)d_in[24]};
    const float* up_r      = (const float*)d_in[25];
    const float* up_w      = (const float*)d_in[26];
    const float* de1w      = (const float*)d_in[27];
    const float* de1b      = (const float*)d_in[28];
    const float* de2w      = (const float*)d_in[29];
    const float* de2b      = (const float*)d_in[30];
    const float* mdp[2]    = {m_p0, m_p1};

    float* bufA = sym(g_bufA);
    float* bufB = sym(g_bufB);
    float* L0   = sym(g_bufL0);
    float* L1   = sym(g_bufL1);
    float* L2   = sym(g_bufL2);
    float* att  = sym(g_att);
    float* vt   = sym(g_vt);
    float* w2   = sym(g_w2);

    // 1. encoder
    encoder_k<<<B_SZ * NFULL, 256>>>(x, en_w, en_b, bufA);

    // 2. down attention: att[H,1024,4096], value from bufA, out -> L0 [B,1024,256]
    softmax_k<NFULL><<<HEADS * NLAT, 256>>>(m_down, down_r, att, NLAT);
    repack_w_k<<<256, 256>>>(down_w, w2);
    {   // value-transpose: [B*4096,256]x[256,256] -> vt[H,4096,B*32]
        dim3 g(4, (B_SZ * NFULL) / 64, 1);
        gemm_k<3><<<g, 256>>>(bufA, w2, vt, nullptr, nullptr,
                              B_SZ * NFULL, CDIM, CDIM, 0, 0, NFULL);
    }
    {   // att@value per head: [1024,4096]x[4096,256], gelu -> L0
        dim3 g(4, NLAT / 64, HEADS);
        gemm_k<4><<<g, 256>>>(att, vt, L0, nullptr, nullptr,
                              NLAT, CDIM, NFULL, (long)NLAT * NFULL, (long)NFULL * CDIM, 0);
    }

    // 3. two latent blocks
    float* hcur = L0;
    float* scratch[2] = {L1, L2};
    for (int blk = 0; blk < 2; blk++) {
        float* pa = scratch[0];
        float* t  = scratch[1];
        pct_att_k<<<HEADS * NLAT, 256>>>(mdp[blk], pa_r[blk], att);
        repack_w_k<<<256, 256>>>(pa_w[blk], w2);
        {   dim3 g(4, (B_SZ * NLAT) / 64, 1);
            gemm_k<3><<<g, 256>>>(hcur, w2, vt, nullptr, nullptr,
                                  B_SZ * NLAT, CDIM, CDIM, 0, 0, NLAT);
        }
        {   dim3 g(4, NLAT / 64, HEADS);
            gemm_k<4><<<g, 256>>>(att, vt, pa, nullptr, nullptr,
                                  NLAT, CDIM, NLAT, (long)NLAT * NLAT, (long)NLAT * CDIM, 0);
        }
        dim3 gl(4, (B_SZ * NLAT) / 64, 1);
        // t = gelu(pa@f1 + b1)
        gemm_k<0><<<gl, 256>>>(pa, f1w[blk], t, f1b[blk], nullptr,
                               B_SZ * NLAT, CDIM, CDIM, 0, 0, 0);
        // pa = t@f2 + b2   (mlp out; pa no longer needed)
        gemm_k<1><<<gl, 256>>>(t, f2w[blk], pa, f2b[blk], nullptr,
                               B_SZ * NLAT, CDIM, CDIM, 0, 0, 0);
        // t = gelu(pa + hcur@rw + rb)
        gemm_k<2><<<gl, 256>>>(hcur, rw[blk], t, rb[blk], pa,
                               B_SZ * NLAT, CDIM, CDIM, 0, 0, 0);
        // rotate: new h = t; free buffers = {old hcur, pa}
        float* newh = t;
        scratch[0] = hcur; scratch[1] = pa;
        hcur = newh;
    }

    // 4. up attention: att[H,4096,1024], value from hcur, out -> bufA [B,4096,256]
    softmax_k<NLAT><<<HEADS * NFULL, 256>>>(m_up, up_r, att, NFULL);
    repack_w_k<<<256, 256>>>(up_w, w2);
    {   dim3 g(4, (B_SZ * NLAT) / 64, 1);
        gemm_k<3><<<g, 256>>>(hcur, w2, vt, nullptr, nullptr,
                              B_SZ * NLAT, CDIM, CDIM, 0, 0, NLAT);
    }
    {   dim3 g(4, NFULL / 64, HEADS);
        gemm_k<4><<<g, 256>>>(att, vt, bufA, nullptr, nullptr,
                              NFULL, CDIM, NLAT, (long)NFULL * NLAT, (long)NLAT * CDIM, 0);
    }

    // 5. decoder
    {   dim3 g(4, (B_SZ * NFULL) / 64, 1);
        gemm_k<0><<<g, 256>>>(bufA, de1w, bufB, de1b, nullptr,
                              B_SZ * NFULL, CDIM, CDIM, 0, 0, 0);
    }
    final_k<<<(B_SZ * NFULL) / 8, 256>>>(bufB, de2w, de2b, (float*)d_out);
}